// round 13
// baseline (speedup 1.0000x reference)
#include <cuda_runtime.h>
#include <cstdint>

#define TT   128
#define BLK  128
#define EPB  64          // elements per block: 4 warps x 16 lane-pairs
#define RSTRIDE 220      // floats per role block in shared

// ---- shared layout (floats) ----
#define FC_OFF 660
#define FW1 (FC_OFF)
#define FB1 (FW1+640)
#define FW2 (FB1+32)
#define FB2 (FW2+1024)
#define FW3 (FB2+32)
#define FB3 (FW3+512)
#define FW4 (FB3+16)
#define FB4 (FW4+256)
#define FW5 (FB4+16)
#define FB5 (FW5+80)
#define S_TOTAL (FB5+5)   // 3273 floats = ~13.1 KB

typedef unsigned long long u64;

__device__ __forceinline__ float tanh_fast(float x) {
    float y;
    asm("tanh.approx.f32 %0, %1;" : "=f"(y) : "f"(x));
    return y;
}
// rows pre-scaled by 0.5 at staging: sigm(a) = fma(tanh(a'), 0.5, 0.5)
__device__ __forceinline__ float sigm_pre(float a_half) {
    return fmaf(tanh_fast(a_half), 0.5f, 0.5f);
}

__device__ __forceinline__ u64 ffma2(u64 a, u64 b, u64 c) {
    u64 d;
    asm("fma.rn.f32x2 %0, %1, %2, %3;" : "=l"(d) : "l"(a), "l"(b), "l"(c));
    return d;
}
__device__ __forceinline__ u64 bcast2(float x) {
    u64 d;
    asm("mov.b64 %0, {%1, %1};" : "=l"(d) : "f"(x));
    return d;
}
__device__ __forceinline__ void unpack2(u64 v, float& lo, float& hi) {
    asm("mov.b64 {%0, %1}, %2;" : "=f"(lo), "=f"(hi) : "l"(v));
}

// One H=5 LSTM cell step, packed gate math (R8 cell, unconditional commit).
// sW: WihT[5][20], WhhT at +100 (i/f/o rows pre-scaled 0.5); sB: pre-scaled fused bias[20].
__device__ __forceinline__ void cell(const float* __restrict__ sW,
                                     const float* __restrict__ sB,
                                     const float* __restrict__ in,
                                     float* __restrict__ h,
                                     float* __restrict__ c) {
    u64 g[10];
    {
        const ulonglong2* b2 = reinterpret_cast<const ulonglong2*>(sB);
        #pragma unroll
        for (int q = 0; q < 5; q++) {
            ulonglong2 v = b2[q];
            g[2*q] = v.x; g[2*q+1] = v.y;
        }
    }
    #pragma unroll
    for (int k = 0; k < 5; k++) {
        u64 xk2 = bcast2(in[k]);
        const ulonglong2* w2 = reinterpret_cast<const ulonglong2*>(sW + k * 20);
        #pragma unroll
        for (int q = 0; q < 5; q++) {
            ulonglong2 w = w2[q];
            g[2*q]   = ffma2(w.x, xk2, g[2*q]);
            g[2*q+1] = ffma2(w.y, xk2, g[2*q+1]);
        }
    }
    #pragma unroll
    for (int k = 0; k < 5; k++) {
        u64 hk2 = bcast2(h[k]);
        const ulonglong2* u2 = reinterpret_cast<const ulonglong2*>(sW + 100 + k * 20);
        #pragma unroll
        for (int q = 0; q < 5; q++) {
            ulonglong2 u = u2[q];
            g[2*q]   = ffma2(u.x, hk2, g[2*q]);
            g[2*q+1] = ffma2(u.y, hk2, g[2*q+1]);
        }
    }
    float ga[20];
    #pragma unroll
    for (int q = 0; q < 10; q++) unpack2(g[q], ga[2*q], ga[2*q+1]);

    #pragma unroll
    for (int m = 0; m < 5; m++) {
        float ig = sigm_pre(ga[m]);
        float fg = sigm_pre(ga[5 + m]);
        float gg = tanh_fast(ga[10 + m]);
        float og = sigm_pre(ga[15 + m]);
        float cm = fmaf(fg, c[m], ig * gg);
        c[m] = cm;
        h[m] = og * tanh_fast(cm);
    }
}

// Load one 2-timestep chunk (10 floats, 8B-aligned) with LDG.64.
__device__ __forceinline__ void load2(float* dst, const float* src) {
    const float2* s2 = reinterpret_cast<const float2*>(src);
    #pragma unroll
    for (int i = 0; i < 5; i++) {
        float2 v = __ldg(s2 + i);
        dst[2*i+0] = v.x; dst[2*i+1] = v.y;
    }
}

struct Params {
    const float *x1, *x2;
    const float *Wih1, *Whh1, *bih1, *bhh1;
    const float *Wih2a, *Whh2a, *bih2a, *bhh2a;
    const float *Wih2b, *Whh2b, *bih2b, *bhh2b;
    const float *W1, *b1, *W2, *b2, *W3, *b3, *W4, *b4, *W5, *b5;
    float* out;
    int B;
};

__global__ __launch_bounds__(BLK)
void dynrnn_kernel(Params p) {
    __shared__ float s[S_TOTAL];
    const int tid = threadIdx.x;

    // ---- cooperative weight staging (transposed LSTM weights, role blocks) ----
    // sigmoid-gate rows (j<10 i/f, j>=15 o) pre-scaled by 0.5
    {
        const float* srcs[6] = { p.Wih1, p.Whh1, p.Wih2a, p.Whh2a, p.Wih2b, p.Whh2b };
        const int    offs[6] = { 0, 100, RSTRIDE, RSTRIDE+100, 2*RSTRIDE, 2*RSTRIDE+100 };
        for (int m = 0; m < 6; m++) {
            const float* W = srcs[m];
            int off = offs[m];
            for (int i = tid; i < 100; i += BLK) {
                int j = i / 5, k = i % 5;
                float sc = (j < 10 || j >= 15) ? 0.5f : 1.0f;
                s[off + k * 20 + j] = W[i] * sc;
            }
        }
        for (int i = tid; i < 20; i += BLK) {
            float sc = (i < 10 || i >= 15) ? 0.5f : 1.0f;
            s[0*RSTRIDE + 200 + i] = (p.bih1[i]  + p.bhh1[i])  * sc;
            s[1*RSTRIDE + 200 + i] = (p.bih2a[i] + p.bhh2a[i]) * sc;
            s[2*RSTRIDE + 200 + i] = (p.bih2b[i] + p.bhh2b[i]) * sc;
        }
        for (int i = tid; i < 640;  i += BLK) s[FW1 + i] = p.W1[i];
        for (int i = tid; i < 32;   i += BLK) s[FB1 + i] = p.b1[i];
        for (int i = tid; i < 1024; i += BLK) s[FW2 + i] = p.W2[i];
        for (int i = tid; i < 32;   i += BLK) s[FB2 + i] = p.b2[i];
        for (int i = tid; i < 512;  i += BLK) s[FW3 + i] = p.W3[i];
        for (int i = tid; i < 16;   i += BLK) s[FB3 + i] = p.b3[i];
        for (int i = tid; i < 256;  i += BLK) s[FW4 + i] = p.W4[i];
        for (int i = tid; i < 16;   i += BLK) s[FB4 + i] = p.b4[i];
        for (int i = tid; i < 80;   i += BLK) s[FW5 + i] = p.W5[i];
        for (int i = tid; i < 5;    i += BLK) s[FB5 + i] = p.b5[i];
    }
    __syncthreads();

    // ---- lane mapping: 2 lanes per element, 16 elements per warp ----
    // even lane: slot1 = lstm1 (x1), slot2 = dummy (lstm2b weights, garbage state)
    // odd  lane: slot1 = lstm2a (x2), slot2 = lstm2b (input = slot1's fresh h — same lane!)
    const int l   = tid & 31;
    const int sub = l & 1;
    const int pr  = l >> 1;          // 0..15

    const int e = blockIdx.x * EPB + (tid >> 5) * 16 + pr;
    const bool valid = (e < p.B);
    const int ec = valid ? e : (p.B - 1);

    const bool odd = (sub == 1);
    const float* __restrict__ xp = (odd ? p.x2 : p.x1) + (size_t)ec * (TT * 5);
    // slot1 weights: lstm1 (even) / lstm2a (odd)
    const float* __restrict__ sW1 = s + (odd ? RSTRIDE : 0);
    const float* __restrict__ sB1 = sW1 + 200;
    // slot2 weights: lstm2b (uniform across lanes — broadcast LDS)
    const float* __restrict__ sW2 = s + 2 * RSTRIDE;
    const float* __restrict__ sB2 = sW2 + 200;

    float h1[5], c1[5];   // slot1 state: lstm1 (even) / lstm2a (odd)
    float h2[5], c2[5];   // slot2 state: dummy (even) / lstm2b (odd)
    #pragma unroll
    for (int m = 0; m < 5; m++) {
        h1[m] = 0.0f; c1[m] = 0.0f; h2[m] = 0.0f; c2[m] = 0.0f;
    }

    float A[10], Bb[10];  // 2-step double buffers, single stream per lane
    load2(A, xp);         // chunk 0 (steps 0,1)

    #pragma unroll 1
    for (int it = 0; it < 32; it++) {
        load2(Bb, xp + (2 * it + 1) * 10);
        #pragma unroll
        for (int tl = 0; tl < 2; tl++) {
            cell(sW1, sB1, &A[tl * 5], h1, c1);   // lstm1 / lstm2a
            cell(sW2, sB2, h1,         h2, c2);   // lstm2b (odd); bounded dummy (even)
        }
        int ci = 2 * it + 2; if (ci > 63) ci = 63;  // clamped redundant load on last iter
        load2(A, xp + ci * 10);
        #pragma unroll
        for (int tl = 0; tl < 2; tl++) {
            cell(sW1, sB1, &Bb[tl * 5], h1, c1);
            cell(sW2, sB2, h1,          h2, c2);
        }
    }

    // ---- gather onto even lanes ----
    // Bb holds chunk 63 (steps 126,127): last-step inputs at Bb[5..9]
    float x2l[5], o2[5];
    #pragma unroll
    for (int j = 0; j < 5; j++) {
        x2l[j] = __shfl_down_sync(0xFFFFFFFFu, Bb[5 + j], 1);  // odd lane: x2 last
        o2[j]  = __shfl_down_sync(0xFFFFFFFFu, h2[j], 1);      // odd lane: out2 (lstm2b)
    }

    if (valid && sub == 0) {
        float a0[20];
        #pragma unroll
        for (int j = 0; j < 5; j++) {
            a0[j]      = Bb[5 + j];  // x1 last
            a0[5 + j]  = x2l[j];     // x2 last
            a0[10 + j] = h1[j];      // out1 (lstm1)
            a0[15 + j] = o2[j];      // out2 (lstm2b)
        }
        float a1[32];
        #pragma unroll
        for (int j = 0; j < 32; j++) {
            float acc = s[FB1 + j];
            #pragma unroll
            for (int k = 0; k < 20; k++) acc = fmaf(s[FW1 + j * 20 + k], a0[k], acc);
            a1[j] = fmaxf(acc, 0.0f);
        }
        float a2[32];
        #pragma unroll
        for (int j = 0; j < 32; j++) {
            float acc = s[FB2 + j];
            #pragma unroll
            for (int k = 0; k < 32; k++) acc = fmaf(s[FW2 + j * 32 + k], a1[k], acc);
            a2[j] = fmaxf(acc, 0.0f);
        }
        float a3[16];
        #pragma unroll
        for (int j = 0; j < 16; j++) {
            float acc = s[FB3 + j];
            #pragma unroll
            for (int k = 0; k < 32; k++) acc = fmaf(s[FW3 + j * 32 + k], a2[k], acc);
            a3[j] = fmaxf(acc, 0.0f);
        }
        float a4[16];
        #pragma unroll
        for (int j = 0; j < 16; j++) {
            float acc = s[FB4 + j];
            #pragma unroll
            for (int k = 0; k < 16; k++) acc = fmaf(s[FW4 + j * 16 + k], a3[k], acc);
            a4[j] = fmaxf(acc, 0.0f);
        }
        #pragma unroll
        for (int j = 0; j < 5; j++) {
            float acc = s[FB5 + j];
            #pragma unroll
            for (int k = 0; k < 16; k++) acc = fmaf(s[FW5 + j * 16 + k], a4[k], acc);
            p.out[(size_t)e * 5 + j] = acc;
        }
    }
}

extern "C" void kernel_launch(void* const* d_in, const int* in_sizes, int n_in,
                              void* d_out, int out_size) {
    Params p;
    p.x1    = (const float*)d_in[0];
    p.x2    = (const float*)d_in[1];
    p.Wih1  = (const float*)d_in[2];
    p.Whh1  = (const float*)d_in[3];
    p.bih1  = (const float*)d_in[4];
    p.bhh1  = (const float*)d_in[5];
    p.Wih2a = (const float*)d_in[6];
    p.Whh2a = (const float*)d_in[7];
    p.bih2a = (const float*)d_in[8];
    p.bhh2a = (const float*)d_in[9];
    p.Wih2b = (const float*)d_in[10];
    p.Whh2b = (const float*)d_in[11];
    p.bih2b = (const float*)d_in[12];
    p.bhh2b = (const float*)d_in[13];
    p.W1 = (const float*)d_in[14];  p.b1 = (const float*)d_in[15];
    p.W2 = (const float*)d_in[16];  p.b2 = (const float*)d_in[17];
    p.W3 = (const float*)d_in[18];  p.b3 = (const float*)d_in[19];
    p.W4 = (const float*)d_in[20];  p.b4 = (const float*)d_in[21];
    p.W5 = (const float*)d_in[22];  p.b5 = (const float*)d_in[23];
    p.out = (float*)d_out;
    p.B   = in_sizes[0] / (TT * 5);

    int grid = (p.B + EPB - 1) / EPB;   // 256 blocks for B=16384 -> single wave
    dynrnn_kernel<<<grid, BLK>>>(p);
}

// round 14
// speedup vs baseline: 1.0890x; 1.0890x over previous
#include <cuda_runtime.h>
#include <cstdint>

#define TT   128
#define BLK  128
#define EPB  80          // elements per block: 4 warps x 10 groups x 2 elems
#define RSTRIDE 220      // floats per role block in shared

// ---- shared layout (floats) ----
#define FC_OFF 660
#define FW1 (FC_OFF)
#define FB1 (FW1+640)
#define FW2 (FB1+32)
#define FB2 (FW2+1024)
#define FW3 (FB2+32)
#define FB3 (FW3+512)
#define FW4 (FB3+16)
#define FB4 (FW4+256)
#define FW5 (FB4+16)
#define FB5 (FW5+80)
#define S_TOTAL (FB5+5)   // 3273 floats = ~13.1 KB

typedef unsigned long long u64;

__device__ __forceinline__ float tanh_fast(float x) {
    float y;
    asm("tanh.approx.f32 %0, %1;" : "=f"(y) : "f"(x));
    return y;
}
// rows pre-scaled by 0.5 at staging: sigm(a) = fma(tanh(a'), 0.5, 0.5)
__device__ __forceinline__ float sigm_pre(float a_half) {
    return fmaf(tanh_fast(a_half), 0.5f, 0.5f);
}

__device__ __forceinline__ u64 ffma2(u64 a, u64 b, u64 c) {
    u64 d;
    asm("fma.rn.f32x2 %0, %1, %2, %3;" : "=l"(d) : "l"(a), "l"(b), "l"(c));
    return d;
}
__device__ __forceinline__ u64 bcast2(float x) {
    u64 d;
    asm("mov.b64 %0, {%1, %1};" : "=l"(d) : "f"(x));
    return d;
}
__device__ __forceinline__ void unpack2(u64 v, float& lo, float& hi) {
    asm("mov.b64 {%0, %1}, %2;" : "=f"(lo), "=f"(hi) : "l"(v));
}

// TWO independent cells of the SAME role (elements A and B), interleaved for ILP.
// sW: WihT[5][20], WhhT at +100 (i/f/o rows pre-scaled 0.5); sB: fused bias[20].
__device__ __forceinline__ void cell2(const float* __restrict__ sW,
                                      const float* __restrict__ sB,
                                      const float* __restrict__ inA,
                                      const float* __restrict__ inB,
                                      float* __restrict__ hA, float* __restrict__ cA,
                                      float* __restrict__ hB, float* __restrict__ cB,
                                      bool commit) {
    u64 gA[10], gB[10];
    {
        const ulonglong2* b2 = reinterpret_cast<const ulonglong2*>(sB);
        #pragma unroll
        for (int q = 0; q < 5; q++) {
            ulonglong2 v = b2[q];
            gA[2*q] = v.x; gA[2*q+1] = v.y;
            gB[2*q] = v.x; gB[2*q+1] = v.y;
        }
    }
    #pragma unroll
    for (int k = 0; k < 5; k++) {
        u64 xa = bcast2(inA[k]);
        u64 xb = bcast2(inB[k]);
        const ulonglong2* w2 = reinterpret_cast<const ulonglong2*>(sW + k * 20);
        #pragma unroll
        for (int q = 0; q < 5; q++) {
            ulonglong2 w = w2[q];
            gA[2*q]   = ffma2(w.x, xa, gA[2*q]);
            gA[2*q+1] = ffma2(w.y, xa, gA[2*q+1]);
            gB[2*q]   = ffma2(w.x, xb, gB[2*q]);
            gB[2*q+1] = ffma2(w.y, xb, gB[2*q+1]);
        }
    }
    #pragma unroll
    for (int k = 0; k < 5; k++) {
        u64 ha = bcast2(hA[k]);
        u64 hb = bcast2(hB[k]);
        const ulonglong2* u2 = reinterpret_cast<const ulonglong2*>(sW + 100 + k * 20);
        #pragma unroll
        for (int q = 0; q < 5; q++) {
            ulonglong2 u = u2[q];
            gA[2*q]   = ffma2(u.x, ha, gA[2*q]);
            gA[2*q+1] = ffma2(u.y, ha, gA[2*q+1]);
            gB[2*q]   = ffma2(u.x, hb, gB[2*q]);
            gB[2*q+1] = ffma2(u.y, hb, gB[2*q+1]);
        }
    }
    float aA[20], aB[20];
    #pragma unroll
    for (int q = 0; q < 10; q++) {
        unpack2(gA[q], aA[2*q], aA[2*q+1]);
        unpack2(gB[q], aB[2*q], aB[2*q+1]);
    }
    #pragma unroll
    for (int m = 0; m < 5; m++) {
        float igA = sigm_pre(aA[m]);
        float fgA = sigm_pre(aA[5 + m]);
        float ggA = tanh_fast(aA[10 + m]);
        float ogA = sigm_pre(aA[15 + m]);
        float cmA = fmaf(fgA, cA[m], igA * ggA);
        float hmA = ogA * tanh_fast(cmA);

        float igB = sigm_pre(aB[m]);
        float fgB = sigm_pre(aB[5 + m]);
        float ggB = tanh_fast(aB[10 + m]);
        float ogB = sigm_pre(aB[15 + m]);
        float cmB = fmaf(fgB, cB[m], igB * ggB);
        float hmB = ogB * tanh_fast(cmB);

        cA[m] = commit ? cmA : cA[m];
        hA[m] = commit ? hmA : hA[m];
        cB[m] = commit ? cmB : cB[m];
        hB[m] = commit ? hmB : hB[m];
    }
}

// Load one 2-timestep chunk (10 floats, 8B-aligned) with LDG.64.
__device__ __forceinline__ void load2(float* dst, const float* src) {
    const float2* s2 = reinterpret_cast<const float2*>(src);
    #pragma unroll
    for (int i = 0; i < 5; i++) {
        float2 v = __ldg(s2 + i);
        dst[2*i+0] = v.x; dst[2*i+1] = v.y;
    }
}

struct Params {
    const float *x1, *x2;
    const float *Wih1, *Whh1, *bih1, *bhh1;
    const float *Wih2a, *Whh2a, *bih2a, *bhh2a;
    const float *Wih2b, *Whh2b, *bih2b, *bhh2b;
    const float *W1, *b1, *W2, *b2, *W3, *b3, *W4, *b4, *W5, *b5;
    float* out;
    int B;
};

__global__ __launch_bounds__(BLK)
void dynrnn_kernel(Params p) {
    __shared__ float s[S_TOTAL];
    const int tid = threadIdx.x;

    // ---- cooperative weight staging (transposed LSTM weights, role blocks) ----
    // sigmoid-gate rows (j<10 i/f, j>=15 o) pre-scaled by 0.5
    {
        const float* srcs[6] = { p.Wih1, p.Whh1, p.Wih2a, p.Whh2a, p.Wih2b, p.Whh2b };
        const int    offs[6] = { 0, 100, RSTRIDE, RSTRIDE+100, 2*RSTRIDE, 2*RSTRIDE+100 };
        for (int m = 0; m < 6; m++) {
            const float* W = srcs[m];
            int off = offs[m];
            for (int i = tid; i < 100; i += BLK) {
                int j = i / 5, k = i % 5;
                float sc = (j < 10 || j >= 15) ? 0.5f : 1.0f;
                s[off + k * 20 + j] = W[i] * sc;
            }
        }
        for (int i = tid; i < 20; i += BLK) {
            float sc = (i < 10 || i >= 15) ? 0.5f : 1.0f;
            s[0*RSTRIDE + 200 + i] = (p.bih1[i]  + p.bhh1[i])  * sc;
            s[1*RSTRIDE + 200 + i] = (p.bih2a[i] + p.bhh2a[i]) * sc;
            s[2*RSTRIDE + 200 + i] = (p.bih2b[i] + p.bhh2b[i]) * sc;
        }
        for (int i = tid; i < 640;  i += BLK) s[FW1 + i] = p.W1[i];
        for (int i = tid; i < 32;   i += BLK) s[FB1 + i] = p.b1[i];
        for (int i = tid; i < 1024; i += BLK) s[FW2 + i] = p.W2[i];
        for (int i = tid; i < 32;   i += BLK) s[FB2 + i] = p.b2[i];
        for (int i = tid; i < 512;  i += BLK) s[FW3 + i] = p.W3[i];
        for (int i = tid; i < 16;   i += BLK) s[FB3 + i] = p.b3[i];
        for (int i = tid; i < 256;  i += BLK) s[FW4 + i] = p.W4[i];
        for (int i = tid; i < 16;   i += BLK) s[FB4 + i] = p.b4[i];
        for (int i = tid; i < 80;   i += BLK) s[FW5 + i] = p.W5[i];
        for (int i = tid; i < 5;    i += BLK) s[FB5 + i] = p.b5[i];
    }
    __syncthreads();

    // ---- lane/role mapping: 3 lanes per 2-element group, 10 groups per warp ----
    const int l   = tid & 31;
    const int grp = l / 3;           // 0..9
    const int r   = l - 3 * grp;     // 0: lstm1, 1: lstm2a, 2: lstm2b
    const bool lane_ok = (l < 30);

    const int eA = blockIdx.x * EPB + (tid >> 5) * 20 + grp * 2;
    const int eB = eA + 1;
    const bool validA = lane_ok && (eA < p.B);
    const bool validB = lane_ok && (eB < p.B);
    const int ecA = (eA < p.B) ? eA : (p.B - 1);
    const int ecB = (eB < p.B) ? eB : (p.B - 1);

    const float* xbase = (r == 1) ? p.x2 : p.x1;
    const float* __restrict__ xpA = xbase + (size_t)ecA * (TT * 5);
    const float* __restrict__ xpB = xbase + (size_t)ecB * (TT * 5);
    const float* __restrict__ sW = s + r * RSTRIDE;
    const float* __restrict__ sB = sW + 200;
    const bool isr2 = (r == 2);

    float hA[5], cA[5], hB[5], cB[5], nhA[5], nhB[5];
    #pragma unroll
    for (int m = 0; m < 5; m++) {
        hA[m] = cA[m] = hB[m] = cB[m] = nhA[m] = nhB[m] = 0.0f;
    }

    float Aa[10], Ab[10], Ba[10], Bb[10];   // 2-step double buffers x 2 elements
    load2(Aa, xpA);
    load2(Ab, xpB);

    #pragma unroll 1
    for (int it = 0; it < 32; it++) {
        load2(Ba, xpA + (2 * it + 1) * 10);
        load2(Bb, xpB + (2 * it + 1) * 10);
        #pragma unroll
        for (int tl = 0; tl < 2; tl++) {
            float inA[5], inB[5];
            #pragma unroll
            for (int j = 0; j < 5; j++) {
                inA[j] = isr2 ? nhA[j] : Aa[tl * 5 + j];
                inB[j] = isr2 ? nhB[j] : Ab[tl * 5 + j];
            }
            bool commit = !(isr2 && (it == 0) && (tl == 0));
            cell2(sW, sB, inA, inB, hA, cA, hB, cB, commit);
            #pragma unroll
            for (int j = 0; j < 5; j++) {
                nhA[j] = __shfl_up_sync(0xFFFFFFFFu, hA[j], 1);
                nhB[j] = __shfl_up_sync(0xFFFFFFFFu, hB[j], 1);
            }
        }
        int ci = 2 * it + 2; if (ci > 63) ci = 63;
        load2(Aa, xpA + ci * 10);
        load2(Ab, xpB + ci * 10);
        #pragma unroll
        for (int tl = 0; tl < 2; tl++) {
            float inA[5], inB[5];
            #pragma unroll
            for (int j = 0; j < 5; j++) {
                inA[j] = isr2 ? nhA[j] : Ba[tl * 5 + j];
                inB[j] = isr2 ? nhB[j] : Bb[tl * 5 + j];
            }
            cell2(sW, sB, inA, inB, hA, cA, hB, cB, true);
            #pragma unroll
            for (int j = 0; j < 5; j++) {
                nhA[j] = __shfl_up_sync(0xFFFFFFFFu, hA[j], 1);
                nhB[j] = __shfl_up_sync(0xFFFFFFFFu, hB[j], 1);
            }
        }
    }

    // role-2 drains the pipeline: final step consumes h2a(127) for both elements
    if (isr2) {
        cell2(sW, sB, nhA, nhB, hA, cA, hB, cB, true);
    }

    // ---- gather onto role-0 lanes ----
    // Ba/Bb hold chunk 63 (steps 126,127): last-step inputs at [5..9]
    float x2lA[5], x2lB[5], o2A[5], o2B[5];
    #pragma unroll
    for (int j = 0; j < 5; j++) {
        x2lA[j] = __shfl_down_sync(0xFFFFFFFFu, Ba[5 + j], 1);  // role 1: x2 last (elem A)
        x2lB[j] = __shfl_down_sync(0xFFFFFFFFu, Bb[5 + j], 1);  // role 1: x2 last (elem B)
        o2A[j]  = __shfl_down_sync(0xFFFFFFFFu, hA[j], 2);      // role 2: out2 (elem A)
        o2B[j]  = __shfl_down_sync(0xFFFFFFFFu, hB[j], 2);      // role 2: out2 (elem B)
    }

    if (r == 0) {
        #pragma unroll 1
        for (int slot = 0; slot < 2; slot++) {
            bool v = (slot == 0) ? validA : validB;
            if (!v) continue;
            int e = (slot == 0) ? eA : eB;
            float a0[20];
            #pragma unroll
            for (int j = 0; j < 5; j++) {
                a0[j]      = (slot == 0) ? Ba[5 + j] : Bb[5 + j];   // x1 last
                a0[5 + j]  = (slot == 0) ? x2lA[j]   : x2lB[j];     // x2 last
                a0[10 + j] = (slot == 0) ? hA[j]     : hB[j];       // out1
                a0[15 + j] = (slot == 0) ? o2A[j]    : o2B[j];      // out2
            }
            float a1[32];
            #pragma unroll
            for (int j = 0; j < 32; j++) {
                float acc = s[FB1 + j];
                #pragma unroll
                for (int k = 0; k < 20; k++) acc = fmaf(s[FW1 + j * 20 + k], a0[k], acc);
                a1[j] = fmaxf(acc, 0.0f);
            }
            float a2[32];
            #pragma unroll
            for (int j = 0; j < 32; j++) {
                float acc = s[FB2 + j];
                #pragma unroll
                for (int k = 0; k < 32; k++) acc = fmaf(s[FW2 + j * 32 + k], a1[k], acc);
                a2[j] = fmaxf(acc, 0.0f);
            }
            float a3[16];
            #pragma unroll
            for (int j = 0; j < 16; j++) {
                float acc = s[FB3 + j];
                #pragma unroll
                for (int k = 0; k < 32; k++) acc = fmaf(s[FW3 + j * 32 + k], a2[k], acc);
                a3[j] = fmaxf(acc, 0.0f);
            }
            float a4[16];
            #pragma unroll
            for (int j = 0; j < 16; j++) {
                float acc = s[FB4 + j];
                #pragma unroll
                for (int k = 0; k < 16; k++) acc = fmaf(s[FW4 + j * 16 + k], a3[k], acc);
                a4[j] = fmaxf(acc, 0.0f);
            }
            #pragma unroll
            for (int j = 0; j < 5; j++) {
                float acc = s[FB5 + j];
                #pragma unroll
                for (int k = 0; k < 16; k++) acc = fmaf(s[FW5 + j * 16 + k], a4[k], acc);
                p.out[(size_t)e * 5 + j] = acc;
            }
        }
    }
}

extern "C" void kernel_launch(void* const* d_in, const int* in_sizes, int n_in,
                              void* d_out, int out_size) {
    Params p;
    p.x1    = (const float*)d_in[0];
    p.x2    = (const float*)d_in[1];
    p.Wih1  = (const float*)d_in[2];
    p.Whh1  = (const float*)d_in[3];
    p.bih1  = (const float*)d_in[4];
    p.bhh1  = (const float*)d_in[5];
    p.Wih2a = (const float*)d_in[6];
    p.Whh2a = (const float*)d_in[7];
    p.bih2a = (const float*)d_in[8];
    p.bhh2a = (const float*)d_in[9];
    p.Wih2b = (const float*)d_in[10];
    p.Whh2b = (const float*)d_in[11];
    p.bih2b = (const float*)d_in[12];
    p.bhh2b = (const float*)d_in[13];
    p.W1 = (const float*)d_in[14];  p.b1 = (const float*)d_in[15];
    p.W2 = (const float*)d_in[16];  p.b2 = (const float*)d_in[17];
    p.W3 = (const float*)d_in[18];  p.b3 = (const float*)d_in[19];
    p.W4 = (const float*)d_in[20];  p.b4 = (const float*)d_in[21];
    p.W5 = (const float*)d_in[22];  p.b5 = (const float*)d_in[23];
    p.out = (float*)d_out;
    p.B   = in_sizes[0] / (TT * 5);

    int grid = (p.B + EPB - 1) / EPB;   // 205 blocks for B=16384 -> single wave
    dynrnn_kernel<<<grid, BLK>>>(p);
}